// round 6
// baseline (speedup 1.0000x reference)
#include <cuda_runtime.h>
#include <math.h>

#define H      2048
#define TSTEPS 1024
#define NCTA   147
#define MAXC   14
#define JPAD   (NCTA * MAXC)      // 2058 padded columns
#define HPAD   2060               // h-buffer stride: 16B-aligned
#define NTH    256                // 7 compute warps + 1 sync warp
#define NWARP  7                  // compute warps

// smem layout (floats): r cols [0,14H) ; z cols 0..12 [14H,27H) ; hbuf [27H,28H) ; flag,cnt
#define ZS_BASE   (14 * H)
#define HBUF_OFF  (27 * H)
#define CTRL_OFF  (28 * H)               // [0]=flag, [1]=cnt
#define SMEM_BYTES ((28 * H + 16) * 4)   // 229,440 B  (< 232,448 limit)

typedef unsigned long long u64;

#define FFMA2(acc, a, b) \
    asm("fma.rn.f32x2 %0, %1, %2, %0;" : "+l"(acc) : "l"(a), "l"(b))

__device__ __forceinline__ float2 unpk(u64 v) {
    float2 r;
    asm("mov.b64 {%0, %1}, %2;" : "=f"(r.x), "=f"(r.y) : "l"(v));
    return r;
}

// ---------------- persistent device state ----------------
__device__ float    g_Wt[3][(size_t)JPAD * H];  // transposed: g_Wt[g][j][k] = Wh_g[k][j]
__device__ float    g_u[3][HPAD];
__device__ float    g_v[3][HPAD];
__device__ float    g_xs[TSTEPS];
__device__ float    g_h[2][HPAD];
__device__ unsigned g_ctr;

// ---------------- memory-order helpers ----------------
__device__ __forceinline__ unsigned ld_relax_g(const unsigned* p) {
    unsigned v;
    asm volatile("ld.relaxed.gpu.global.b32 %0, [%1];" : "=r"(v) : "l"(p) : "memory");
    return v;
}
__device__ __forceinline__ unsigned ld_acq_g(const unsigned* p) {
    unsigned v;
    asm volatile("ld.acquire.gpu.global.b32 %0, [%1];" : "=r"(v) : "l"(p) : "memory");
    return v;
}
__device__ __forceinline__ void red_rel_add_g(unsigned* p, unsigned v) {
    asm volatile("red.release.gpu.global.add.u32 [%0], %1;" :: "l"(p), "r"(v) : "memory");
}
__device__ __forceinline__ unsigned ld_acq_s(unsigned saddr) {
    unsigned v;
    asm volatile("ld.acquire.cta.shared.u32 %0, [%1];" : "=r"(v) : "r"(saddr) : "memory");
    return v;
}
__device__ __forceinline__ void st_rel_s(unsigned saddr, unsigned v) {
    asm volatile("st.release.cta.shared.u32 [%0], %1;" :: "r"(saddr), "r"(v) : "memory");
}
__device__ __forceinline__ unsigned atom_acqrel_add_s(unsigned saddr, unsigned v) {
    unsigned old;
    asm volatile("atom.acq_rel.cta.shared.add.u32 %0, [%1], %2;"
                 : "=r"(old) : "r"(saddr), "r"(v) : "memory");
    return old;
}

// ---------------- init ----------------
__global__ void init_kernel(const float* __restrict__ x) {
    int t = threadIdx.x;              // 0..1023
    int row = t >> 5;
    int c = t & 31;
    int oc = (row & 1) ? (31 - c) : c;
    g_xs[t] = x[(row << 5) + oc];
    for (int i = t; i < HPAD; i += 1024) { g_h[0][i] = 0.0f; g_h[1][i] = 0.0f; }
    for (int i = t; i < 3 * HPAD; i += 1024) {
        ((float*)g_u)[i] = 0.0f;
        ((float*)g_v)[i] = 0.0f;
    }
    if (t == 0) g_ctr = 0u;
}

// ---------------- transpose Whr/Whz/Whn into g_Wt (column-major) ----------------
__global__ void transpose_kernel(const float* __restrict__ Whr,
                                 const float* __restrict__ Whz,
                                 const float* __restrict__ Whn) {
    __shared__ float tile[32][33];
    const float* src = (blockIdx.z == 0) ? Whr : (blockIdx.z == 1) ? Whz : Whn;
    float* dst = g_Wt[blockIdx.z];
    int k0 = blockIdx.x * 32;
    int j0 = blockIdx.y * 32;
    #pragma unroll
    for (int i = 0; i < 32; i += 8)
        tile[threadIdx.y + i][threadIdx.x] =
            src[(size_t)(k0 + threadIdx.y + i) * H + j0 + threadIdx.x];
    __syncthreads();
    #pragma unroll
    for (int i = 0; i < 32; i += 8)
        dst[(size_t)(j0 + threadIdx.y + i) * H + k0 + threadIdx.x] =
            tile[threadIdx.x][threadIdx.y + i];
}

// ---------------- prep ----------------
__global__ void prep_kernel(const float* __restrict__ We, const float* __restrict__ be,
                            const float* __restrict__ Wir, const float* __restrict__ bir,
                            const float* __restrict__ Wiz, const float* __restrict__ biz,
                            const float* __restrict__ Win, const float* __restrict__ bin_) {
    int j  = blockIdx.x * 128 + threadIdx.x;
    int k0 = blockIdx.y * 128;
    float u0 = 0, v0 = 0, u1 = 0, v1 = 0, u2 = 0, v2 = 0;
    for (int k = k0; k < k0 + 128; k++) {
        float we = We[k];
        float b  = be[k];
        float w;
        w = Wir[(size_t)k * H + j]; u0 = fmaf(we, w, u0); v0 = fmaf(b, w, v0);
        w = Wiz[(size_t)k * H + j]; u1 = fmaf(we, w, u1); v1 = fmaf(b, w, v1);
        w = Win[(size_t)k * H + j]; u2 = fmaf(we, w, u2); v2 = fmaf(b, w, v2);
    }
    if (blockIdx.y == 0) { v0 += bir[j]; v1 += biz[j]; v2 += bin_[j]; }
    atomicAdd(&g_u[0][j], u0); atomicAdd(&g_v[0][j], v0);
    atomicAdd(&g_u[1][j], u1); atomicAdd(&g_v[1][j], v1);
    atomicAdd(&g_u[2][j], u2); atomicAdd(&g_v[2][j], v2);
}

// ---------------- persistent recurrent kernel ----------------
extern __shared__ float sw[];

__global__ void __launch_bounds__(NTH, 1) gru_kernel(const float* __restrict__ bhn,
                                                     float* __restrict__ out) {
    const int cta  = blockIdx.x;
    const int tid  = threadIdx.x;
    const int warp = tid >> 5;
    const int lane = tid & 31;
    const int cb   = cta * MAXC;

    unsigned* ctrl = (unsigned*)(sw + CTRL_OFF);
    const unsigned flag_sa = (unsigned)__cvta_generic_to_shared(&ctrl[0]);
    const unsigned cnt_sa  = (unsigned)__cvta_generic_to_shared(&ctrl[1]);
    if (tid == 0) { ctrl[0] = 0u; ctrl[1] = 0u; }

    // ---- preload weights: r cols 0..13, z cols 0..12 into SMEM ----
    {
        const float4* s0 = (const float4*)(g_Wt[0] + (size_t)cb * H);   // 14 r cols
        const float4* s1 = (const float4*)(g_Wt[1] + (size_t)cb * H);   // 13 z cols
        float4* d0 = (float4*)sw;
        float4* d1 = (float4*)(sw + ZS_BASE);
        const int n4r = 14 * H / 4;
        const int n4z = 13 * H / 4;
        for (int i = tid; i < n4r; i += NTH) d0[i] = s0[i];
        for (int i = tid; i < n4z; i += NTH) d1[i] = s1[i];
    }

    // ---- this warp's 2 columns (compute warps 0..6) ----
    const int cw = (warp < NWARP) ? warp : 0;       // sync warp aliases warp0 (math unused)
    const int c0 = 2 * cw, c1 = c0 + 1;
    const int j0 = cb + c0, j1 = cb + c1;

    // ---- Whn columns resident in registers (constant across steps) ----
    ulonglong2 wn0[16], wn1[16];
    {
        const ulonglong2* p0 = (const ulonglong2*)(g_Wt[2] + (size_t)j0 * H);
        const ulonglong2* p1 = (const ulonglong2*)(g_Wt[2] + (size_t)j1 * H);
        #pragma unroll
        for (int i = 0; i < 16; i++) { wn0[i] = p0[lane + 32 * i]; wn1[i] = p1[lane + 32 * i]; }
    }

    // ---- epilogue constants on lanes 0,1 ----
    const int jj = (lane == 0) ? j0 : j1;
    float ur = 0, vr = 0, uz = 0, vz = 0, un = 0, vn = 0, bh = 0, hprev = 0.0f;
    if (lane < 2) {
        int js = (jj < H) ? jj : (H - 1);
        ur = g_u[0][js]; vr = g_v[0][js];
        uz = g_u[1][js]; vz = g_v[1][js];
        un = g_u[2][js]; vn = g_v[2][js];
        bh = bhn[js];
    }

    const ulonglong2* sr0 = (const ulonglong2*)(sw + (size_t)c0 * H);
    const ulonglong2* sr1 = (const ulonglong2*)(sw + (size_t)c1 * H);
    const ulonglong2* sz0 = (const ulonglong2*)(sw + (size_t)(ZS_BASE + c0 * H));
    const ulonglong2* sz1 = (const ulonglong2*)(sw + (size_t)(ZS_BASE + c1 * H)); // warp6: unused
    const ulonglong2* gz1 = (const ulonglong2*)(g_Wt[1] + (size_t)(cb + 13) * H); // warp6's z col
    const ulonglong2* hb  = (const ulonglong2*)(sw + HBUF_OFF);
    __syncthreads();   // smem weights + ctrl ready

    for (int t = 1; t <= TSTEPS; t++) {
        const int rb = (t - 1) & 1;
        const int wb = t & 1;

        // ---- warp6: prefetch first chunk of streamed z column (step-invariant,
        //      independent of the barrier) so L2 latency hides under the sync ----
        ulonglong2 dpre[4];
        if (warp == 6) {
            #pragma unroll
            for (int i = 0; i < 4; i++) dpre[i] = __ldcg(gz1 + lane + 32 * i);
        }

        // ---- sync warp (7): poll global counter, publish smem flag ----
        if (warp == 7 && lane == 0) {
            if (t > 1) {
                const unsigned tgt = (unsigned)(t - 1) * NCTA;
                while (ld_relax_g(&g_ctr) < tgt) { }
                (void)ld_acq_g(&g_ctr);    // ordering edge (gpu scope)
            }
            st_rel_s(flag_sa, (unsigned)t);
        }
        // all warps wait on the smem flag (broadcast LDS)
        while (ld_acq_s(flag_sa) < (unsigned)t) { }

        // ---- cooperative fill: h[rb] global -> smem hbuf (512 float4) ----
        {
            const float4* hsrc = (const float4*)g_h[rb];
            float4* hdst = (float4*)(sw + HBUF_OFF);
            #pragma unroll
            for (int i = tid; i < 512; i += NTH) hdst[i] = __ldcg(hsrc + i);
        }
        __syncthreads();   // hbuf ready

        float xt = __ldg(&g_xs[t - 1]);

        // ---- h into registers from smem ----
        ulonglong2 h2[16];
        #pragma unroll
        for (int i = 0; i < 16; i++) h2[i] = hb[lane + 32 * i];

        // ---- fused 6-dot loop ----
        u64 ar0 = 0, ar1 = 0, az0 = 0, az1 = 0, an0 = 0, an1 = 0;
        if (warp < 6) {
            #pragma unroll
            for (int i = 0; i < 16; i++) {
                u64 hA = h2[i].x, hB = h2[i].y;
                ulonglong2 a = sr0[lane + 32 * i];
                ulonglong2 b = sr1[lane + 32 * i];
                ulonglong2 c = sz0[lane + 32 * i];
                ulonglong2 d = sz1[lane + 32 * i];
                FFMA2(ar0, hA, a.x); FFMA2(ar0, hB, a.y);
                FFMA2(ar1, hA, b.x); FFMA2(ar1, hB, b.y);
                FFMA2(az0, hA, c.x); FFMA2(az0, hB, c.y);
                FFMA2(az1, hA, d.x); FFMA2(az1, hB, d.y);
                FFMA2(an0, hA, wn0[i].x); FFMA2(an0, hB, wn0[i].y);
                FFMA2(an1, hA, wn1[i].x); FFMA2(an1, hB, wn1[i].y);
            }
        } else if (warp == 6) {
            // software-pipelined: consume chunk c while prefetching chunk c+1
            #pragma unroll
            for (int c = 0; c < 4; c++) {
                ulonglong2 dcur[4];
                #pragma unroll
                for (int i = 0; i < 4; i++) dcur[i] = dpre[i];
                if (c < 3) {
                    #pragma unroll
                    for (int i = 0; i < 4; i++)
                        dpre[i] = __ldcg(gz1 + lane + 32 * (4 * (c + 1) + i));
                }
                #pragma unroll
                for (int i = 0; i < 4; i++) {
                    int it = 4 * c + i;
                    u64 hA = h2[it].x, hB = h2[it].y;
                    ulonglong2 a = sr0[lane + 32 * it];
                    ulonglong2 b = sr1[lane + 32 * it];
                    ulonglong2 cc = sz0[lane + 32 * it];
                    ulonglong2 d = dcur[i];
                    FFMA2(ar0, hA, a.x); FFMA2(ar0, hB, a.y);
                    FFMA2(ar1, hA, b.x); FFMA2(ar1, hB, b.y);
                    FFMA2(az0, hA, cc.x); FFMA2(az0, hB, cc.y);
                    FFMA2(az1, hA, d.x); FFMA2(az1, hB, d.y);
                    FFMA2(an0, hA, wn0[it].x); FFMA2(an0, hB, wn0[it].y);
                    FFMA2(an1, hA, wn1[it].x); FFMA2(an1, hB, wn1[it].y);
                }
            }
        }

        if (warp < NWARP) {
            // ---- collapse pairs; reduce r/z first so sigmoids can start early ----
            float2 pr0 = unpk(ar0), pr1 = unpk(ar1);
            float2 pz0 = unpk(az0), pz1 = unpk(az1);
            float Ar0 = pr0.x + pr0.y, Ar1 = pr1.x + pr1.y;
            float Az0 = pz0.x + pz0.y, Az1 = pz1.x + pz1.y;
            #pragma unroll
            for (int s = 16; s > 0; s >>= 1) {
                Ar0 += __shfl_xor_sync(0xffffffffu, Ar0, s);
                Ar1 += __shfl_xor_sync(0xffffffffu, Ar1, s);
                Az0 += __shfl_xor_sync(0xffffffffu, Az0, s);
                Az1 += __shfl_xor_sync(0xffffffffu, Az1, s);
            }
            // all lanes compute (no guard) — overlaps with the An reduce below
            float dr = (lane == 0) ? Ar0 : Ar1;
            float dz = (lane == 0) ? Az0 : Az1;
            float ar = fmaf(xt, ur, vr) + dr;
            float az = fmaf(xt, uz, vz) + dz;
            float r = __fdividef(1.0f, 1.0f + __expf(-ar));
            float z = __fdividef(1.0f, 1.0f + __expf(-az));

            float2 pn0 = unpk(an0), pn1 = unpk(an1);
            float An0 = pn0.x + pn0.y, An1 = pn1.x + pn1.y;
            #pragma unroll
            for (int s = 16; s > 0; s >>= 1) {
                An0 += __shfl_xor_sync(0xffffffffu, An0, s);
                An1 += __shfl_xor_sync(0xffffffffu, An1, s);
            }
            float dn = (lane == 0) ? An0 : An1;
            float an = fmaf(xt, un, vn);
            float v = an + r * (dn + bh);
            float n = 1.0f - __fdividef(2.0f, 1.0f + __expf(2.0f * v));  // tanh(v)
            float hn = (1.0f - z) * n + z * hprev;
            hprev = hn;
            if (lane < 2 && jj < H) {
                __stcg(&g_h[wb][jj], hn);
                if (t == TSTEPS) out[jj] = hn;
            }
            __syncwarp();   // order lane1's store before lane0's release

            // ---- publish: per-warp cta-release arrival; winner does gpu release ----
            if (lane == 0) {
                unsigned old = atom_acqrel_add_s(cnt_sa, 1u);
                if (old == (unsigned)(NWARP * t - 1)) red_rel_add_g(&g_ctr, 1u);
            }
        }
    }
}

// ---------------- host launch ----------------
extern "C" void kernel_launch(void* const* d_in, const int* in_sizes, int n_in,
                              void* d_out, int out_size) {
    const float* x    = (const float*)d_in[0];
    const float* We   = (const float*)d_in[1];
    const float* be   = (const float*)d_in[2];
    const float* Wir  = (const float*)d_in[3];
    const float* bir  = (const float*)d_in[4];
    const float* Wiz  = (const float*)d_in[5];
    const float* biz  = (const float*)d_in[6];
    const float* Win  = (const float*)d_in[7];
    const float* bin_ = (const float*)d_in[8];
    const float* Whr  = (const float*)d_in[9];
    const float* Whz  = (const float*)d_in[10];
    const float* Whn  = (const float*)d_in[11];
    const float* bhn  = (const float*)d_in[12];
    float* out = (float*)d_out;

    cudaFuncSetAttribute(gru_kernel, cudaFuncAttributeMaxDynamicSharedMemorySize,
                         SMEM_BYTES);

    init_kernel<<<1, 1024>>>(x);
    transpose_kernel<<<dim3(H / 32, H / 32, 3), dim3(32, 8)>>>(Whr, Whz, Whn);
    prep_kernel<<<dim3(H / 128, H / 128), 128>>>(We, be, Wir, bir, Wiz, biz, Win, bin_);
    gru_kernel<<<NCTA, NTH, SMEM_BYTES>>>(bhn, out);
}

// round 8
// speedup vs baseline: 1.1053x; 1.1053x over previous
#include <cuda_runtime.h>
#include <math.h>

#define H      2048
#define TSTEPS 1024
#define NCTA   147
#define MAXC   14
#define JPAD   (NCTA * MAXC)      // 2058 padded columns
#define HPAD   2060               // h-buffer stride: 16B-aligned
#define NTH    224                // 7 warps, 2 columns each
#define NWARP  7

// smem layout (floats): r cols [0,14H) ; z cols 0..12 [14H,27H) ; hbuf [27H,28H) ; flag,cnt
#define ZS_BASE   (14 * H)
#define HBUF_OFF  (27 * H)
#define CTRL_OFF  (28 * H)               // [0]=flag, [1]=cnt
#define SMEM_BYTES ((28 * H + 16) * 4)   // 229,440 B

typedef unsigned long long u64;

#define FFMA2(acc, a, b) \
    asm("fma.rn.f32x2 %0, %1, %2, %0;" : "+l"(acc) : "l"(a), "l"(b))

__device__ __forceinline__ float2 unpk(u64 v) {
    float2 r;
    asm("mov.b64 {%0, %1}, %2;" : "=f"(r.x), "=f"(r.y) : "l"(v));
    return r;
}

// ---------------- persistent device state ----------------
__device__ float    g_Wt[3][(size_t)JPAD * H];  // transposed: g_Wt[g][j][k] = Wh_g[k][j]
__device__ float    g_u[3][HPAD];
__device__ float    g_v[3][HPAD];
__device__ float    g_xs[TSTEPS];
__device__ float    g_h[2][HPAD];
__device__ unsigned g_ctr;

// ---------------- memory-order helpers ----------------
__device__ __forceinline__ unsigned ld_relax_g(const unsigned* p) {
    unsigned v;
    asm volatile("ld.relaxed.gpu.global.b32 %0, [%1];" : "=r"(v) : "l"(p) : "memory");
    return v;
}
__device__ __forceinline__ unsigned ld_acq_g(const unsigned* p) {
    unsigned v;
    asm volatile("ld.acquire.gpu.global.b32 %0, [%1];" : "=r"(v) : "l"(p) : "memory");
    return v;
}
__device__ __forceinline__ void red_rel_add_g(unsigned* p, unsigned v) {
    asm volatile("red.release.gpu.global.add.u32 [%0], %1;" :: "l"(p), "r"(v) : "memory");
}
__device__ __forceinline__ unsigned ld_acq_s(unsigned saddr) {
    unsigned v;
    asm volatile("ld.acquire.cta.shared.u32 %0, [%1];" : "=r"(v) : "r"(saddr) : "memory");
    return v;
}
__device__ __forceinline__ void st_rel_s(unsigned saddr, unsigned v) {
    asm volatile("st.release.cta.shared.u32 [%0], %1;" :: "r"(saddr), "r"(v) : "memory");
}
__device__ __forceinline__ unsigned atom_acqrel_add_s(unsigned saddr, unsigned v) {
    unsigned old;
    asm volatile("atom.acq_rel.cta.shared.add.u32 %0, [%1], %2;"
                 : "=r"(old) : "r"(saddr), "r"(v) : "memory");
    return old;
}

// ---------------- init ----------------
__global__ void init_kernel(const float* __restrict__ x) {
    int t = threadIdx.x;              // 0..1023
    int row = t >> 5;
    int c = t & 31;
    int oc = (row & 1) ? (31 - c) : c;
    g_xs[t] = x[(row << 5) + oc];
    for (int i = t; i < HPAD; i += 1024) { g_h[0][i] = 0.0f; g_h[1][i] = 0.0f; }
    for (int i = t; i < 3 * HPAD; i += 1024) {
        ((float*)g_u)[i] = 0.0f;
        ((float*)g_v)[i] = 0.0f;
    }
    if (t == 0) g_ctr = 0u;
}

// ---------------- transpose Whr/Whz/Whn into g_Wt (column-major) ----------------
__global__ void transpose_kernel(const float* __restrict__ Whr,
                                 const float* __restrict__ Whz,
                                 const float* __restrict__ Whn) {
    __shared__ float tile[32][33];
    const float* src = (blockIdx.z == 0) ? Whr : (blockIdx.z == 1) ? Whz : Whn;
    float* dst = g_Wt[blockIdx.z];
    int k0 = blockIdx.x * 32;
    int j0 = blockIdx.y * 32;
    #pragma unroll
    for (int i = 0; i < 32; i += 8)
        tile[threadIdx.y + i][threadIdx.x] =
            src[(size_t)(k0 + threadIdx.y + i) * H + j0 + threadIdx.x];
    __syncthreads();
    #pragma unroll
    for (int i = 0; i < 32; i += 8)
        dst[(size_t)(j0 + threadIdx.y + i) * H + k0 + threadIdx.x] =
            tile[threadIdx.x][threadIdx.y + i];
}

// ---------------- prep ----------------
__global__ void prep_kernel(const float* __restrict__ We, const float* __restrict__ be,
                            const float* __restrict__ Wir, const float* __restrict__ bir,
                            const float* __restrict__ Wiz, const float* __restrict__ biz,
                            const float* __restrict__ Win, const float* __restrict__ bin_) {
    int j  = blockIdx.x * 128 + threadIdx.x;
    int k0 = blockIdx.y * 128;
    float u0 = 0, v0 = 0, u1 = 0, v1 = 0, u2 = 0, v2 = 0;
    for (int k = k0; k < k0 + 128; k++) {
        float we = We[k];
        float b  = be[k];
        float w;
        w = Wir[(size_t)k * H + j]; u0 = fmaf(we, w, u0); v0 = fmaf(b, w, v0);
        w = Wiz[(size_t)k * H + j]; u1 = fmaf(we, w, u1); v1 = fmaf(b, w, v1);
        w = Win[(size_t)k * H + j]; u2 = fmaf(we, w, u2); v2 = fmaf(b, w, v2);
    }
    if (blockIdx.y == 0) { v0 += bir[j]; v1 += biz[j]; v2 += bin_[j]; }
    atomicAdd(&g_u[0][j], u0); atomicAdd(&g_v[0][j], v0);
    atomicAdd(&g_u[1][j], u1); atomicAdd(&g_v[1][j], v1);
    atomicAdd(&g_u[2][j], u2); atomicAdd(&g_v[2][j], v2);
}

// ---------------- persistent recurrent kernel ----------------
extern __shared__ float sw[];

__global__ void __launch_bounds__(NTH, 1) gru_kernel(const float* __restrict__ bhn,
                                                     float* __restrict__ out) {
    const int cta  = blockIdx.x;
    const int tid  = threadIdx.x;
    const int warp = tid >> 5;
    const int lane = tid & 31;
    const int cb   = cta * MAXC;

    unsigned* ctrl = (unsigned*)(sw + CTRL_OFF);
    const unsigned flag_sa = (unsigned)__cvta_generic_to_shared(&ctrl[0]);
    const unsigned cnt_sa  = (unsigned)__cvta_generic_to_shared(&ctrl[1]);
    if (tid == 0) { ctrl[0] = 0u; ctrl[1] = 0u; }

    // ---- preload weights: r cols 0..13, z cols 0..12 into SMEM ----
    {
        const float4* s0 = (const float4*)(g_Wt[0] + (size_t)cb * H);   // 14 r cols
        const float4* s1 = (const float4*)(g_Wt[1] + (size_t)cb * H);   // 13 z cols
        float4* d0 = (float4*)sw;
        float4* d1 = (float4*)(sw + ZS_BASE);
        const int n4r = 14 * H / 4;
        const int n4z = 13 * H / 4;
        for (int i = tid; i < n4r; i += NTH) d0[i] = s0[i];
        for (int i = tid; i < n4z; i += NTH) d1[i] = s1[i];
    }

    // ---- this warp's 2 columns ----
    const int c0 = 2 * warp, c1 = c0 + 1;
    const int j0 = cb + c0, j1 = cb + c1;

    // ---- Whn columns resident in registers (constant across steps) ----
    ulonglong2 wn0[16], wn1[16];
    {
        const ulonglong2* p0 = (const ulonglong2*)(g_Wt[2] + (size_t)j0 * H);
        const ulonglong2* p1 = (const ulonglong2*)(g_Wt[2] + (size_t)j1 * H);
        #pragma unroll
        for (int i = 0; i < 16; i++) { wn0[i] = p0[lane + 32 * i]; wn1[i] = p1[lane + 32 * i]; }
    }

    // ---- epilogue constants on lanes 0,1 ----
    const int jj = (lane == 0) ? j0 : j1;
    float ur = 0, vr = 0, uz = 0, vz = 0, un = 0, vn = 0, bh = 0, hprev = 0.0f;
    if (lane < 2) {
        int js = (jj < H) ? jj : (H - 1);
        ur = g_u[0][js]; vr = g_v[0][js];
        uz = g_u[1][js]; vz = g_v[1][js];
        un = g_u[2][js]; vn = g_v[2][js];
        bh = bhn[js];
    }

    const ulonglong2* sr0 = (const ulonglong2*)(sw + (size_t)c0 * H);
    const ulonglong2* sr1 = (const ulonglong2*)(sw + (size_t)c1 * H);
    const ulonglong2* sz0 = (const ulonglong2*)(sw + (size_t)(ZS_BASE + c0 * H));
    const ulonglong2* sz1 = (const ulonglong2*)(sw + (size_t)(ZS_BASE + c1 * H)); // warp6: unused
    const ulonglong2* gz1 = (const ulonglong2*)(g_Wt[1] + (size_t)(cb + 13) * H); // warp6's z col
    const ulonglong2* hb  = (const ulonglong2*)(sw + HBUF_OFF);
    __syncthreads();   // smem weights + ctrl ready

    for (int t = 1; t <= TSTEPS; t++) {
        const int rb = (t - 1) & 1;
        const int wb = t & 1;

        // ---- warp6: prefetch chunk0 of streamed z col (step-invariant) BEFORE spin ----
        ulonglong2 dpre[4];
        if (warp == 6) {
            #pragma unroll
            for (int i = 0; i < 4; i++) dpre[i] = __ldcg(gz1 + lane + 32 * i);
        }

        // ---- barrier: warp0 lane0 polls global counter, publishes smem flag ----
        if (warp == 0 && lane == 0) {
            if (t > 1) {
                const unsigned tgt = (unsigned)(t - 1) * NCTA;
                while (ld_relax_g(&g_ctr) < tgt) { }
                (void)ld_acq_g(&g_ctr);    // ordering edge (gpu scope)
            }
            st_rel_s(flag_sa, (unsigned)t);
        }
        while (ld_acq_s(flag_sa) < (unsigned)t) { }

        // ---- phase A: fill h[0:1024] -> smem; phase B: issue h[1024:2048] into regs ----
        const float4* hsrc = (const float4*)g_h[rb];
        float4* hdst = (float4*)(sw + HBUF_OFF);
        {
            #pragma unroll
            for (int i = tid; i < 256; i += NTH) hdst[i] = __ldcg(hsrc + i);
        }
        float4 bA = __ldcg(hsrc + 256 + tid);                       // 256..479
        float4 bB;
        if (tid < 32) bB = __ldcg(hsrc + 480 + tid);                // 480..511
        __syncthreads();   // phase A visible

        float xt = __ldg(&g_xs[t - 1]);

        // ---- dot iters 0..7 on phase A (phase-B LDGs in flight) ----
        u64 ar0 = 0, ar1 = 0, az0 = 0, az1 = 0, an0 = 0, an1 = 0;
        if (warp < 6) {
            #pragma unroll
            for (int i = 0; i < 8; i++) {
                ulonglong2 h = hb[lane + 32 * i];
                u64 hA = h.x, hB = h.y;
                ulonglong2 a = sr0[lane + 32 * i];
                ulonglong2 b = sr1[lane + 32 * i];
                ulonglong2 c = sz0[lane + 32 * i];
                ulonglong2 d = sz1[lane + 32 * i];
                FFMA2(ar0, hA, a.x); FFMA2(ar0, hB, a.y);
                FFMA2(ar1, hA, b.x); FFMA2(ar1, hB, b.y);
                FFMA2(az0, hA, c.x); FFMA2(az0, hB, c.y);
                FFMA2(az1, hA, d.x); FFMA2(az1, hB, d.y);
                FFMA2(an0, hA, wn0[i].x); FFMA2(an0, hB, wn0[i].y);
                FFMA2(an1, hA, wn1[i].x); FFMA2(an1, hB, wn1[i].y);
            }
        } else {
            #pragma unroll
            for (int c = 0; c < 2; c++) {
                ulonglong2 dcur[4];
                #pragma unroll
                for (int i = 0; i < 4; i++) dcur[i] = dpre[i];
                #pragma unroll
                for (int i = 0; i < 4; i++)
                    dpre[i] = __ldcg(gz1 + lane + 32 * (4 * (c + 1) + i));
                #pragma unroll
                for (int i = 0; i < 4; i++) {
                    int it = 4 * c + i;
                    ulonglong2 h = hb[lane + 32 * it];
                    u64 hA = h.x, hB = h.y;
                    ulonglong2 a = sr0[lane + 32 * it];
                    ulonglong2 b = sr1[lane + 32 * it];
                    ulonglong2 cc = sz0[lane + 32 * it];
                    ulonglong2 d = dcur[i];
                    FFMA2(ar0, hA, a.x); FFMA2(ar0, hB, a.y);
                    FFMA2(ar1, hA, b.x); FFMA2(ar1, hB, b.y);
                    FFMA2(az0, hA, cc.x); FFMA2(az0, hB, cc.y);
                    FFMA2(az1, hA, d.x); FFMA2(az1, hB, d.y);
                    FFMA2(an0, hA, wn0[it].x); FFMA2(an0, hB, wn0[it].y);
                    FFMA2(an1, hA, wn1[it].x); FFMA2(an1, hB, wn1[it].y);
                }
            }
        }

        // ---- land phase B in smem ----
        hdst[256 + tid] = bA;
        if (tid < 32) hdst[480 + tid] = bB;
        __syncthreads();   // phase B visible

        // ---- dot iters 8..15 on phase B ----
        if (warp < 6) {
            #pragma unroll
            for (int i = 8; i < 16; i++) {
                ulonglong2 h = hb[lane + 32 * i];
                u64 hA = h.x, hB = h.y;
                ulonglong2 a = sr0[lane + 32 * i];
                ulonglong2 b = sr1[lane + 32 * i];
                ulonglong2 c = sz0[lane + 32 * i];
                ulonglong2 d = sz1[lane + 32 * i];
                FFMA2(ar0, hA, a.x); FFMA2(ar0, hB, a.y);
                FFMA2(ar1, hA, b.x); FFMA2(ar1, hB, b.y);
                FFMA2(az0, hA, c.x); FFMA2(az0, hB, c.y);
                FFMA2(az1, hA, d.x); FFMA2(az1, hB, d.y);
                FFMA2(an0, hA, wn0[i].x); FFMA2(an0, hB, wn0[i].y);
                FFMA2(an1, hA, wn1[i].x); FFMA2(an1, hB, wn1[i].y);
            }
        } else {
            #pragma unroll
            for (int c = 2; c < 4; c++) {
                ulonglong2 dcur[4];
                #pragma unroll
                for (int i = 0; i < 4; i++) dcur[i] = dpre[i];
                if (c < 3) {
                    #pragma unroll
                    for (int i = 0; i < 4; i++)
                        dpre[i] = __ldcg(gz1 + lane + 32 * (4 * (c + 1) + i));
                }
                #pragma unroll
                for (int i = 0; i < 4; i++) {
                    int it = 4 * c + i;
                    ulonglong2 h = hb[lane + 32 * it];
                    u64 hA = h.x, hB = h.y;
                    ulonglong2 a = sr0[lane + 32 * it];
                    ulonglong2 b = sr1[lane + 32 * it];
                    ulonglong2 cc = sz0[lane + 32 * it];
                    ulonglong2 d = dcur[i];
                    FFMA2(ar0, hA, a.x); FFMA2(ar0, hB, a.y);
                    FFMA2(ar1, hA, b.x); FFMA2(ar1, hB, b.y);
                    FFMA2(az0, hA, cc.x); FFMA2(az0, hB, cc.y);
                    FFMA2(az1, hA, d.x); FFMA2(az1, hB, d.y);
                    FFMA2(an0, hA, wn0[it].x); FFMA2(an0, hB, wn0[it].y);
                    FFMA2(an1, hA, wn1[it].x); FFMA2(an1, hB, wn1[it].y);
                }
            }
        }

        // ---- collapse pairs; reduce r/z first so sigmoids start early ----
        float2 pr0 = unpk(ar0), pr1 = unpk(ar1);
        float2 pz0 = unpk(az0), pz1 = unpk(az1);
        float Ar0 = pr0.x + pr0.y, Ar1 = pr1.x + pr1.y;
        float Az0 = pz0.x + pz0.y, Az1 = pz1.x + pz1.y;
        #pragma unroll
        for (int s = 16; s > 0; s >>= 1) {
            Ar0 += __shfl_xor_sync(0xffffffffu, Ar0, s);
            Ar1 += __shfl_xor_sync(0xffffffffu, Ar1, s);
            Az0 += __shfl_xor_sync(0xffffffffu, Az0, s);
            Az1 += __shfl_xor_sync(0xffffffffu, Az1, s);
        }
        float dr = (lane == 0) ? Ar0 : Ar1;
        float dz = (lane == 0) ? Az0 : Az1;
        float ar = fmaf(xt, ur, vr) + dr;
        float az = fmaf(xt, uz, vz) + dz;
        float r = __fdividef(1.0f, 1.0f + __expf(-ar));
        float z = __fdividef(1.0f, 1.0f + __expf(-az));

        float2 pn0 = unpk(an0), pn1 = unpk(an1);
        float An0 = pn0.x + pn0.y, An1 = pn1.x + pn1.y;
        #pragma unroll
        for (int s = 16; s > 0; s >>= 1) {
            An0 += __shfl_xor_sync(0xffffffffu, An0, s);
            An1 += __shfl_xor_sync(0xffffffffu, An1, s);
        }
        float dn = (lane == 0) ? An0 : An1;
        float an = fmaf(xt, un, vn);
        float v = an + r * (dn + bh);
        float n = 1.0f - __fdividef(2.0f, 1.0f + __expf(2.0f * v));  // tanh(v)
        float hn = (1.0f - z) * n + z * hprev;
        hprev = hn;
        if (lane < 2 && jj < H) {
            __stcg(&g_h[wb][jj], hn);
            if (t == TSTEPS) out[jj] = hn;
        }
        __syncwarp();   // order lane1's store before lane0's release

        // ---- publish: per-warp cta-release arrival; winner does gpu release ----
        if (lane == 0) {
            unsigned old = atom_acqrel_add_s(cnt_sa, 1u);
            if (old == (unsigned)(NWARP * t - 1)) red_rel_add_g(&g_ctr, 1u);
        }
    }
}

// ---------------- host launch ----------------
extern "C" void kernel_launch(void* const* d_in, const int* in_sizes, int n_in,
                              void* d_out, int out_size) {
    const float* x    = (const float*)d_in[0];
    const float* We   = (const float*)d_in[1];
    const float* be   = (const float*)d_in[2];
    const float* Wir  = (const float*)d_in[3];
    const float* bir  = (const float*)d_in[4];
    const float* Wiz  = (const float*)d_in[5];
    const float* biz  = (const float*)d_in[6];
    const float* Win  = (const float*)d_in[7];
    const float* bin_ = (const float*)d_in[8];
    const float* Whr  = (const float*)d_in[9];
    const float* Whz  = (const float*)d_in[10];
    const float* Whn  = (const float*)d_in[11];
    const float* bhn  = (const float*)d_in[12];
    float* out = (float*)d_out;

    cudaFuncSetAttribute(gru_kernel, cudaFuncAttributeMaxDynamicSharedMemorySize,
                         SMEM_BYTES);

    init_kernel<<<1, 1024>>>(x);
    transpose_kernel<<<dim3(H / 32, H / 32, 3), dim3(32, 8)>>>(Whr, Whz, Whn);
    prep_kernel<<<dim3(H / 128, H / 128), 128>>>(We, be, Wir, bir, Wiz, biz, Win, bin_);
    gru_kernel<<<NCTA, NTH, SMEM_BYTES>>>(bhn, out);
}

// round 10
// speedup vs baseline: 1.1235x; 1.0164x over previous
#include <cuda_runtime.h>
#include <math.h>

#define H      2048
#define TSTEPS 1024
#define NCTA   147
#define MAXC   14
#define JPAD   (NCTA * MAXC)      // 2058 padded columns
#define HPAD   2060
#define HREP   8                  // h replicas (consumers read cta&7)
#define HRS    2176               // replica stride in floats (16B aligned, slice-spread)
#define NTH    224                // 7 warps, 2 columns each
#define NWARP  7

// smem layout (floats): r cols [0,14H) ; z cols 0..12 [14H,27H) ; hbuf [27H,28H) ; flag,cnt
#define ZS_BASE   (14 * H)
#define HBUF_OFF  (27 * H)
#define CTRL_OFF  (28 * H)               // [0]=flag, [1]=cnt
#define SMEM_BYTES ((28 * H + 16) * 4)   // 229,440 B

typedef unsigned long long u64;

#define FFMA2(acc, a, b) \
    asm("fma.rn.f32x2 %0, %1, %2, %0;" : "+l"(acc) : "l"(a), "l"(b))

__device__ __forceinline__ float2 unpk(u64 v) {
    float2 r;
    asm("mov.b64 {%0, %1}, %2;" : "=f"(r.x), "=f"(r.y) : "l"(v));
    return r;
}

// ---------------- persistent device state ----------------
__device__ float    g_Wt[3][(size_t)JPAD * H];  // transposed: g_Wt[g][j][k] = Wh_g[k][j]
__device__ float    g_u[3][HPAD];
__device__ float    g_v[3][HPAD];
__device__ float    g_xs[TSTEPS];
__device__ float    g_hrep[2][HREP][HRS];       // replicated double-buffered h
__device__ unsigned g_ctr;

// ---------------- memory-order helpers ----------------
__device__ __forceinline__ unsigned ld_relax_g(const unsigned* p) {
    unsigned v;
    asm volatile("ld.relaxed.gpu.global.b32 %0, [%1];" : "=r"(v) : "l"(p) : "memory");
    return v;
}
__device__ __forceinline__ unsigned ld_acq_g(const unsigned* p) {
    unsigned v;
    asm volatile("ld.acquire.gpu.global.b32 %0, [%1];" : "=r"(v) : "l"(p) : "memory");
    return v;
}
__device__ __forceinline__ void red_rel_add_g(unsigned* p, unsigned v) {
    asm volatile("red.release.gpu.global.add.u32 [%0], %1;" :: "l"(p), "r"(v) : "memory");
}
__device__ __forceinline__ unsigned ld_acq_s(unsigned saddr) {
    unsigned v;
    asm volatile("ld.acquire.cta.shared.u32 %0, [%1];" : "=r"(v) : "r"(saddr) : "memory");
    return v;
}
__device__ __forceinline__ void st_rel_s(unsigned saddr, unsigned v) {
    asm volatile("st.release.cta.shared.u32 [%0], %1;" :: "r"(saddr), "r"(v) : "memory");
}
__device__ __forceinline__ unsigned atom_acqrel_add_s(unsigned saddr, unsigned v) {
    unsigned old;
    asm volatile("atom.acq_rel.cta.shared.add.u32 %0, [%1], %2;"
                 : "=r"(old) : "r"(saddr), "r"(v) : "memory");
    return old;
}

// ---------------- init ----------------
__global__ void init_kernel(const float* __restrict__ x) {
    int t = threadIdx.x;              // 0..1023
    int row = t >> 5;
    int c = t & 31;
    int oc = (row & 1) ? (31 - c) : c;
    g_xs[t] = x[(row << 5) + oc];
    for (int i = t; i < 2 * HREP * HRS; i += 1024)
        ((float*)g_hrep)[i] = 0.0f;
    for (int i = t; i < 3 * HPAD; i += 1024) {
        ((float*)g_u)[i] = 0.0f;
        ((float*)g_v)[i] = 0.0f;
    }
    if (t == 0) g_ctr = 0u;
}

// ---------------- transpose Whr/Whz/Whn into g_Wt (column-major) ----------------
__global__ void transpose_kernel(const float* __restrict__ Whr,
                                 const float* __restrict__ Whz,
                                 const float* __restrict__ Whn) {
    __shared__ float tile[32][33];
    const float* src = (blockIdx.z == 0) ? Whr : (blockIdx.z == 1) ? Whz : Whn;
    float* dst = g_Wt[blockIdx.z];
    int k0 = blockIdx.x * 32;
    int j0 = blockIdx.y * 32;
    #pragma unroll
    for (int i = 0; i < 32; i += 8)
        tile[threadIdx.y + i][threadIdx.x] =
            src[(size_t)(k0 + threadIdx.y + i) * H + j0 + threadIdx.x];
    __syncthreads();
    #pragma unroll
    for (int i = 0; i < 32; i += 8)
        dst[(size_t)(j0 + threadIdx.y + i) * H + k0 + threadIdx.x] =
            tile[threadIdx.x][threadIdx.y + i];
}

// ---------------- prep ----------------
__global__ void prep_kernel(const float* __restrict__ We, const float* __restrict__ be,
                            const float* __restrict__ Wir, const float* __restrict__ bir,
                            const float* __restrict__ Wiz, const float* __restrict__ biz,
                            const float* __restrict__ Win, const float* __restrict__ bin_) {
    int j  = blockIdx.x * 128 + threadIdx.x;
    int k0 = blockIdx.y * 128;
    float u0 = 0, v0 = 0, u1 = 0, v1 = 0, u2 = 0, v2 = 0;
    for (int k = k0; k < k0 + 128; k++) {
        float we = We[k];
        float b  = be[k];
        float w;
        w = Wir[(size_t)k * H + j]; u0 = fmaf(we, w, u0); v0 = fmaf(b, w, v0);
        w = Wiz[(size_t)k * H + j]; u1 = fmaf(we, w, u1); v1 = fmaf(b, w, v1);
        w = Win[(size_t)k * H + j]; u2 = fmaf(we, w, u2); v2 = fmaf(b, w, v2);
    }
    if (blockIdx.y == 0) { v0 += bir[j]; v1 += biz[j]; v2 += bin_[j]; }
    atomicAdd(&g_u[0][j], u0); atomicAdd(&g_v[0][j], v0);
    atomicAdd(&g_u[1][j], u1); atomicAdd(&g_v[1][j], v1);
    atomicAdd(&g_u[2][j], u2); atomicAdd(&g_v[2][j], v2);
}

// ---------------- persistent recurrent kernel ----------------
extern __shared__ float sw[];

__global__ void __launch_bounds__(NTH, 1) gru_kernel(const float* __restrict__ bhn,
                                                     float* __restrict__ out) {
    const int cta  = blockIdx.x;
    const int tid  = threadIdx.x;
    const int warp = tid >> 5;
    const int lane = tid & 31;
    const int cb   = cta * MAXC;
    const int rep  = cta & (HREP - 1);

    unsigned* ctrl = (unsigned*)(sw + CTRL_OFF);
    const unsigned flag_sa = (unsigned)__cvta_generic_to_shared(&ctrl[0]);
    const unsigned cnt_sa  = (unsigned)__cvta_generic_to_shared(&ctrl[1]);
    if (tid == 0) { ctrl[0] = 0u; ctrl[1] = 0u; }

    // ---- preload weights: r cols 0..13, z cols 0..12 into SMEM ----
    {
        const float4* s0 = (const float4*)(g_Wt[0] + (size_t)cb * H);   // 14 r cols
        const float4* s1 = (const float4*)(g_Wt[1] + (size_t)cb * H);   // 13 z cols
        float4* d0 = (float4*)sw;
        float4* d1 = (float4*)(sw + ZS_BASE);
        const int n4r = 14 * H / 4;
        const int n4z = 13 * H / 4;
        for (int i = tid; i < n4r; i += NTH) d0[i] = s0[i];
        for (int i = tid; i < n4z; i += NTH) d1[i] = s1[i];
    }

    // ---- this warp's 2 columns ----
    const int c0 = 2 * warp, c1 = c0 + 1;
    const int j0 = cb + c0, j1 = cb + c1;

    // ---- Whn columns resident in registers (constant across steps) ----
    ulonglong2 wn0[16], wn1[16];
    {
        const ulonglong2* p0 = (const ulonglong2*)(g_Wt[2] + (size_t)j0 * H);
        const ulonglong2* p1 = (const ulonglong2*)(g_Wt[2] + (size_t)j1 * H);
        #pragma unroll
        for (int i = 0; i < 16; i++) { wn0[i] = p0[lane + 32 * i]; wn1[i] = p1[lane + 32 * i]; }
    }

    // ---- epilogue constants on lanes 0,1 ----
    const int jj = (lane == 0) ? j0 : j1;
    float ur = 0, vr = 0, uz = 0, vz = 0, un = 0, vn = 0, bh = 0, hprev = 0.0f;
    if (lane < 2) {
        int js = (jj < H) ? jj : (H - 1);
        ur = g_u[0][js]; vr = g_v[0][js];
        uz = g_u[1][js]; vz = g_v[1][js];
        un = g_u[2][js]; vn = g_v[2][js];
        bh = bhn[js];
    }

    const ulonglong2* sr0 = (const ulonglong2*)(sw + (size_t)c0 * H);
    const ulonglong2* sr1 = (const ulonglong2*)(sw + (size_t)c1 * H);
    const ulonglong2* sz0 = (const ulonglong2*)(sw + (size_t)(ZS_BASE + c0 * H));
    const ulonglong2* sz1 = (const ulonglong2*)(sw + (size_t)(ZS_BASE + c1 * H)); // warp6: unused
    const ulonglong2* gz1 = (const ulonglong2*)(g_Wt[1] + (size_t)(cb + 13) * H); // warp6's z col
    const ulonglong2* hb  = (const ulonglong2*)(sw + HBUF_OFF);
    const int rotA = (cta * 5) & 255;   // stagger line sweep across CTAs
    __syncthreads();   // smem weights + ctrl ready

    for (int t = 1; t <= TSTEPS; t++) {
        const int rb = (t - 1) & 1;
        const int wb = t & 1;

        float xt = __ldg(&g_xs[t - 1]);   // barrier-independent

        // ---- warp6: prefetch chunk0 of streamed z col (step-invariant) BEFORE spin ----
        ulonglong2 dpre[4];
        if (warp == 6) {
            #pragma unroll
            for (int i = 0; i < 4; i++) dpre[i] = __ldcg(gz1 + lane + 32 * i);
        }

        // ---- barrier: warp0 lane0 polls global counter, publishes smem flag ----
        if (warp == 0 && lane == 0) {
            if (t > 1) {
                const unsigned tgt = (unsigned)(t - 1) * NCTA;
                while (ld_relax_g(&g_ctr) < tgt) { }
                (void)ld_acq_g(&g_ctr);    // ordering edge (gpu scope)
            }
            st_rel_s(flag_sa, (unsigned)t);
        }
        while (ld_acq_s(flag_sa) < (unsigned)t) { }

        // ---- phase A: fill h[0:1024] -> smem (rotated sweep); phase B into regs ----
        const float4* hsrc = (const float4*)g_hrep[rb][rep];
        float4* hdst = (float4*)(sw + HBUF_OFF);
        {
            #pragma unroll
            for (int i = tid; i < 256; i += NTH) {
                int s = (i + rotA) & 255;
                hdst[s] = __ldcg(hsrc + s);
            }
        }
        float4 bA = __ldcg(hsrc + 256 + tid);                       // 256..479
        float4 bB;
        if (tid < 32) bB = __ldcg(hsrc + 480 + tid);                // 480..511
        __syncthreads();   // phase A visible

        // ---- dot iters 0..7 on phase A (phase-B LDGs in flight) ----
        u64 ar0 = 0, ar1 = 0, az0 = 0, az1 = 0, an0 = 0, an1 = 0;
        if (warp < 6) {
            #pragma unroll
            for (int i = 0; i < 8; i++) {
                ulonglong2 h = hb[lane + 32 * i];
                u64 hA = h.x, hB = h.y;
                ulonglong2 a = sr0[lane + 32 * i];
                ulonglong2 b = sr1[lane + 32 * i];
                ulonglong2 c = sz0[lane + 32 * i];
                ulonglong2 d = sz1[lane + 32 * i];
                FFMA2(ar0, hA, a.x); FFMA2(ar0, hB, a.y);
                FFMA2(ar1, hA, b.x); FFMA2(ar1, hB, b.y);
                FFMA2(az0, hA, c.x); FFMA2(az0, hB, c.y);
                FFMA2(az1, hA, d.x); FFMA2(az1, hB, d.y);
                FFMA2(an0, hA, wn0[i].x); FFMA2(an0, hB, wn0[i].y);
                FFMA2(an1, hA, wn1[i].x); FFMA2(an1, hB, wn1[i].y);
            }
        } else {
            #pragma unroll
            for (int c = 0; c < 2; c++) {
                ulonglong2 dcur[4];
                #pragma unroll
                for (int i = 0; i < 4; i++) dcur[i] = dpre[i];
                #pragma unroll
                for (int i = 0; i < 4; i++)
                    dpre[i] = __ldcg(gz1 + lane + 32 * (4 * (c + 1) + i));
                #pragma unroll
                for (int i = 0; i < 4; i++) {
                    int it = 4 * c + i;
                    ulonglong2 h = hb[lane + 32 * it];
                    u64 hA = h.x, hB = h.y;
                    ulonglong2 a = sr0[lane + 32 * it];
                    ulonglong2 b = sr1[lane + 32 * it];
                    ulonglong2 cc = sz0[lane + 32 * it];
                    ulonglong2 d = dcur[i];
                    FFMA2(ar0, hA, a.x); FFMA2(ar0, hB, a.y);
                    FFMA2(ar1, hA, b.x); FFMA2(ar1, hB, b.y);
                    FFMA2(az0, hA, cc.x); FFMA2(az0, hB, cc.y);
                    FFMA2(az1, hA, d.x); FFMA2(az1, hB, d.y);
                    FFMA2(an0, hA, wn0[it].x); FFMA2(an0, hB, wn0[it].y);
                    FFMA2(an1, hA, wn1[it].x); FFMA2(an1, hB, wn1[it].y);
                }
            }
        }

        // ---- land phase B in smem ----
        hdst[256 + tid] = bA;
        if (tid < 32) hdst[480 + tid] = bB;
        __syncthreads();   // phase B visible

        // ---- dot iters 8..15 on phase B ----
        if (warp < 6) {
            #pragma unroll
            for (int i = 8; i < 16; i++) {
                ulonglong2 h = hb[lane + 32 * i];
                u64 hA = h.x, hB = h.y;
                ulonglong2 a = sr0[lane + 32 * i];
                ulonglong2 b = sr1[lane + 32 * i];
                ulonglong2 c = sz0[lane + 32 * i];
                ulonglong2 d = sz1[lane + 32 * i];
                FFMA2(ar0, hA, a.x); FFMA2(ar0, hB, a.y);
                FFMA2(ar1, hA, b.x); FFMA2(ar1, hB, b.y);
                FFMA2(az0, hA, c.x); FFMA2(az0, hB, c.y);
                FFMA2(az1, hA, d.x); FFMA2(az1, hB, d.y);
                FFMA2(an0, hA, wn0[i].x); FFMA2(an0, hB, wn0[i].y);
                FFMA2(an1, hA, wn1[i].x); FFMA2(an1, hB, wn1[i].y);
            }
        } else {
            #pragma unroll
            for (int c = 2; c < 4; c++) {
                ulonglong2 dcur[4];
                #pragma unroll
                for (int i = 0; i < 4; i++) dcur[i] = dpre[i];
                if (c < 3) {
                    #pragma unroll
                    for (int i = 0; i < 4; i++)
                        dpre[i] = __ldcg(gz1 + lane + 32 * (4 * (c + 1) + i));
                }
                #pragma unroll
                for (int i = 0; i < 4; i++) {
                    int it = 4 * c + i;
                    ulonglong2 h = hb[lane + 32 * it];
                    u64 hA = h.x, hB = h.y;
                    ulonglong2 a = sr0[lane + 32 * it];
                    ulonglong2 b = sr1[lane + 32 * it];
                    ulonglong2 cc = sz0[lane + 32 * it];
                    ulonglong2 d = dcur[i];
                    FFMA2(ar0, hA, a.x); FFMA2(ar0, hB, a.y);
                    FFMA2(ar1, hA, b.x); FFMA2(ar1, hB, b.y);
                    FFMA2(az0, hA, cc.x); FFMA2(az0, hB, cc.y);
                    FFMA2(az1, hA, d.x); FFMA2(az1, hB, d.y);
                    FFMA2(an0, hA, wn0[it].x); FFMA2(an0, hB, wn0[it].y);
                    FFMA2(an1, hA, wn1[it].x); FFMA2(an1, hB, wn1[it].y);
                }
            }
        }

        // ---- collapse pairs; reduce r/z first so sigmoids start early ----
        float2 pr0 = unpk(ar0), pr1 = unpk(ar1);
        float2 pz0 = unpk(az0), pz1 = unpk(az1);
        float Ar0 = pr0.x + pr0.y, Ar1 = pr1.x + pr1.y;
        float Az0 = pz0.x + pz0.y, Az1 = pz1.x + pz1.y;
        #pragma unroll
        for (int s = 16; s > 0; s >>= 1) {
            Ar0 += __shfl_xor_sync(0xffffffffu, Ar0, s);
            Ar1 += __shfl_xor_sync(0xffffffffu, Ar1, s);
            Az0 += __shfl_xor_sync(0xffffffffu, Az0, s);
            Az1 += __shfl_xor_sync(0xffffffffu, Az1, s);
        }
        float dr = (lane == 0) ? Ar0 : Ar1;
        float dz = (lane == 0) ? Az0 : Az1;
        float ar = fmaf(xt, ur, vr) + dr;
        float az = fmaf(xt, uz, vz) + dz;
        float r = __fdividef(1.0f, 1.0f + __expf(-ar));
        float z = __fdividef(1.0f, 1.0f + __expf(-az));

        float2 pn0 = unpk(an0), pn1 = unpk(an1);
        float An0 = pn0.x + pn0.y, An1 = pn1.x + pn1.y;
        #pragma unroll
        for (int s = 16; s > 0; s >>= 1) {
            An0 += __shfl_xor_sync(0xffffffffu, An0, s);
            An1 += __shfl_xor_sync(0xffffffffu, An1, s);
        }
        float dn = (lane == 0) ? An0 : An1;
        float an = fmaf(xt, un, vn);
        float v = an + r * (dn + bh);
        float n = 1.0f - __fdividef(2.0f, 1.0f + __expf(2.0f * v));  // tanh(v)
        float hn = (1.0f - z) * n + z * hprev;
        hprev = hn;
        if (lane < 2 && jj < H) {
            // write all replicas (scattered 4B stores, cheap)
            #pragma unroll
            for (int rr = 0; rr < HREP; rr++)
                __stcg(&g_hrep[wb][rr][jj], hn);
            if (t == TSTEPS) out[jj] = hn;
        }
        __syncwarp();   // order lane1's stores before lane0's release

        // ---- publish: per-warp cta-release arrival; winner does gpu release ----
        if (lane == 0) {
            unsigned old = atom_acqrel_add_s(cnt_sa, 1u);
            if (old == (unsigned)(NWARP * t - 1)) red_rel_add_g(&g_ctr, 1u);
        }
    }
}

// ---------------- host launch ----------------
extern "C" void kernel_launch(void* const* d_in, const int* in_sizes, int n_in,
                              void* d_out, int out_size) {
    const float* x    = (const float*)d_in[0];
    const float* We   = (const float*)d_in[1];
    const float* be   = (const float*)d_in[2];
    const float* Wir  = (const float*)d_in[3];
    const float* bir  = (const float*)d_in[4];
    const float* Wiz  = (const float*)d_in[5];
    const float* biz  = (const float*)d_in[6];
    const float* Win  = (const float*)d_in[7];
    const float* bin_ = (const float*)d_in[8];
    const float* Whr  = (const float*)d_in[9];
    const float* Whz  = (const float*)d_in[10];
    const float* Whn  = (const float*)d_in[11];
    const float* bhn  = (const float*)d_in[12];
    float* out = (float*)d_out;

    cudaFuncSetAttribute(gru_kernel, cudaFuncAttributeMaxDynamicSharedMemorySize,
                         SMEM_BYTES);

    init_kernel<<<1, 1024>>>(x);
    transpose_kernel<<<dim3(H / 32, H / 32, 3), dim3(32, 8)>>>(Whr, Whz, Whn);
    prep_kernel<<<dim3(H / 128, H / 128), 128>>>(We, be, Wir, bir, Wiz, biz, Win, bin_);
    gru_kernel<<<NCTA, NTH, SMEM_BYTES>>>(bhn, out);
}